// round 9
// baseline (speedup 1.0000x reference)
#include <cuda_runtime.h>
#include <cuda_bf16.h>

// Problem: B=128, T=512, E=8, H=2, dk=4. N = B*T = 65536 rows.
#define TT 512
#define KSPLIT 4
#define QPB 64
// block = 128 threads = 32 query-pairs x 4 key-splits; grid = 128*8 = 1024.

typedef unsigned long long u64;

// ---- f32x2 packed helpers ----------
__device__ __forceinline__ u64 pack2(float lo, float hi) {
    u64 r; asm("mov.b64 %0, {%1, %2};" : "=l"(r) : "f"(lo), "f"(hi)); return r;
}
__device__ __forceinline__ void unpack2(u64 v, float& lo, float& hi) {
    asm("mov.b64 {%0, %1}, %2;" : "=f"(lo), "=f"(hi) : "l"(v));
}
__device__ __forceinline__ u64 mul2(u64 a, u64 b) {
    u64 r; asm("mul.rn.f32x2 %0, %1, %2;" : "=l"(r) : "l"(a), "l"(b)); return r;
}
__device__ __forceinline__ u64 fma2(u64 a, u64 b, u64 c) {
    u64 r; asm("fma.rn.f32x2 %0, %1, %2, %3;" : "=l"(r) : "l"(a), "l"(b), "l"(c)); return r;
}
__device__ __forceinline__ u64 add2(u64 a, u64 b) {
    u64 r; asm("add.rn.f32x2 %0, %1, %2;" : "=l"(r) : "l"(a), "l"(b)); return r;
}
__device__ __forceinline__ float ex2(float x) {
    float r; asm("ex2.approx.ftz.f32 %0, %1;" : "=f"(r) : "f"(x)); return r;
}

// qlayer closed form: given c[w]=cos(alpha_w):
// out[0]=c1*...*c7 ; out[w>=1]=c0*...*cw
__device__ __forceinline__ void qlayer_from_cos(const float c[8], float o[8]) {
    float t = c[1] * c[2];
    t *= c[3]; t *= c[4]; t *= c[5]; t *= c[6]; t *= c[7];
    o[0] = t;
    float p = c[0] * c[1];
    o[1] = p;
    p *= c[2]; o[2] = p;
    p *= c[3]; o[3] = p;
    p *= c[4]; o[4] = p;
    p *= c[5]; o[5] = p;
    p *= c[6]; o[6] = p;
    p *= c[7]; o[7] = p;
}

struct SmemConsts {
    float Win[64], Wout[64];
    float bin[8], bout[8], l1w[8], l1b[8], l2w[8], l2b[8], tha[8], thf[8];
};

// Full per-row epilogue: ctx -> output row. noinline so its register
// pressure does not inflate the mainloop allocation.
__device__ __noinline__ void epilogue_row(
    const float* __restrict__ ctx, const float* __restrict__ xr,
    float* __restrict__ orow, const SmemConsts& C
) {
    float xv[8];
    {
        float4 e = *reinterpret_cast<const float4*>(xr);
        float4 f = *reinterpret_cast<const float4*>(xr + 4);
        xv[0]=e.x; xv[1]=e.y; xv[2]=e.z; xv[3]=e.w;
        xv[4]=f.x; xv[5]=f.y; xv[6]=f.z; xv[7]=f.w;
    }
    float c[8];
#pragma unroll
    for (int w = 0; w < 8; w++) c[w] = __cosf(ctx[w] + C.tha[w]);
    float ao[8];
    qlayer_from_cos(c, ao);

    float s[8], x1[8];
    float m = 0.0f;
#pragma unroll
    for (int w = 0; w < 8; w++) { s[w] = ao[w] + xv[w]; m += s[w]; }
    m *= 0.125f;
    float v = 0.0f;
#pragma unroll
    for (int w = 0; w < 8; w++) { float d = s[w] - m; v += d * d; }
    v *= 0.125f;
    float istd = rsqrtf(v + 1e-5f);
#pragma unroll
    for (int w = 0; w < 8; w++) x1[w] = (s[w] - m) * istd * C.l1w[w] + C.l1b[w];

    float hq[8];
#pragma unroll
    for (int i = 0; i < 8; i++) {
        float acc = C.bin[i];
#pragma unroll
        for (int j = 0; j < 8; j++) acc += x1[j] * C.Win[i * 8 + j];
        hq[i] = acc;
    }

    // ffn qlayer, wires [0,1,2,2,4,5,6,7]
    float cf[8];
    cf[0] = __cosf(hq[0] + C.thf[0]);
    cf[1] = __cosf(hq[1] + C.thf[1]);
    cf[2] = __cosf(hq[2] + hq[3] + C.thf[2]);
    cf[3] = __cosf(C.thf[3]);
    cf[4] = __cosf(hq[4] + C.thf[4]);
    cf[5] = __cosf(hq[5] + C.thf[5]);
    cf[6] = __cosf(hq[6] + C.thf[6]);
    cf[7] = __cosf(hq[7] + C.thf[7]);
    float qf[8];
    qlayer_from_cos(cf, qf);

    float s2[8];
    float m2 = 0.0f;
#pragma unroll
    for (int i = 0; i < 8; i++) {
        float acc = C.bout[i];
#pragma unroll
        for (int j = 0; j < 8; j++) acc += qf[j] * C.Wout[i * 8 + j];
        s2[i] = acc + x1[i];
        m2 += s2[i];
    }
    m2 *= 0.125f;
    float v2 = 0.0f;
#pragma unroll
    for (int i = 0; i < 8; i++) { float d = s2[i] - m2; v2 += d * d; }
    v2 *= 0.125f;
    float istd2 = rsqrtf(v2 + 1e-5f);

    float res[8];
#pragma unroll
    for (int i = 0; i < 8; i++)
        res[i] = (s2[i] - m2) * istd2 * C.l2w[i] + C.l2b[i];

    *reinterpret_cast<float4*>(orow)     = make_float4(res[0], res[1], res[2], res[3]);
    *reinterpret_cast<float4*>(orow + 4) = make_float4(res[4], res[5], res[6], res[7]);
}

// ---------------------------------------------------------------------------
// Fully fused kernel. grid = 1024 (128 batches x 8 chunks of 64 queries),
// block = 128 threads. Thread = (query-pair p in [0,32), key-split s in [0,4)):
//   queries qa = chunk*64 + p, qb = qa + 32; keys [s*128, (s+1)*128).
// Both heads ride the f32x2 lanes (lane0 = head0, lane1 = head1).
// Each 32B key LDS amortized over 2 queries (G=2). launch_bounds(128,5) =
// 102-reg budget fits the ~95-reg loop (no spill, verified round 8); grid
// 1024 at 5 blocks/SM doubles resident warps vs round 8's grid-limited 512.
// ---------------------------------------------------------------------------
__global__ __launch_bounds__(128, 5) void fused_kernel(
    const float* __restrict__ x,
    const float* __restrict__ thetas_attn,
    const float* __restrict__ thetas_ffn,
    const float* __restrict__ W_in,
    const float* __restrict__ b_in,
    const float* __restrict__ W_out,
    const float* __restrict__ b_out,
    const float* __restrict__ ln1w, const float* __restrict__ ln1b,
    const float* __restrict__ ln2w, const float* __restrict__ ln2b,
    float* __restrict__ out
) {
    __shared__ ulonglong2 Kpk[TT][2];  // lane-packed keys: (h0 dim_i, h1 dim_i)
    __shared__ SmemConsts C;

    const int tid   = threadIdx.x;
    const int b     = blockIdx.x >> 3;
    const int chunk = blockIdx.x & 7;

    if (tid < 64) { C.Win[tid] = W_in[tid]; C.Wout[tid] = W_out[tid]; }
    else if (tid < 72) {
        int i = tid - 64;
        C.bin[i] = b_in[i];  C.bout[i] = b_out[i];
        C.l1w[i] = ln1w[i];  C.l1b[i] = ln1b[i];
        C.l2w[i] = ln2w[i];  C.l2b[i] = ln2b[i];
        C.tha[i] = thetas_attn[i]; C.thf[i] = thetas_ffn[i];
    }

    float th[8];
#pragma unroll
    for (int w = 0; w < 8; w++) th[w] = thetas_attn[w];

    // Prologue: build all 512 keys (both heads) for this batch.
#pragma unroll
    for (int rr = 0; rr < TT / 128; rr++) {
        int i = tid + rr * 128;
        const float* xr = x + ((size_t)(b * TT + i)) * 8;
        float4 xa = *reinterpret_cast<const float4*>(xr);
        float4 xb = *reinterpret_cast<const float4*>(xr + 4);
        float c[8];
        c[0] = __cosf(xa.x + th[0]);
        c[1] = __cosf(xa.y + th[1]);
        c[2] = __cosf(xa.z + th[2]);
        c[3] = __cosf(xa.w + th[3]);
        c[4] = __cosf(xb.x + th[4]);
        c[5] = __cosf(xb.y + th[5]);
        c[6] = __cosf(xb.z + th[6]);
        c[7] = __cosf(xb.w + th[7]);
        float o[8];
        qlayer_from_cos(c, o);
        ulonglong2 p0, p1;
        p0.x = pack2(o[0], o[4]);
        p0.y = pack2(o[1], o[5]);
        p1.x = pack2(o[2], o[6]);
        p1.y = pack2(o[3], o[7]);
        Kpk[i][0] = p0;
        Kpk[i][1] = p1;
    }
    __syncthreads();

    const int s    = tid & 3;              // key split
    const int pair = tid >> 2;             // 0..31
    const int qi0  = chunk * QPB + pair;   // query A
    const int qi1  = qi0 + 32;             // query B

    // Queries pre-scaled by 0.5*log2(e) (softmax scale 1/sqrt(dk)=0.5 folded).
    const float SC = 0.72134752044f;
    const u64 SC2 = pack2(SC, SC);
    ulonglong2 qAa = Kpk[qi0][0], qAb = Kpk[qi0][1];
    ulonglong2 qBa = Kpk[qi1][0], qBb = Kpk[qi1][1];
    u64 qA0 = mul2(qAa.x, SC2), qA1 = mul2(qAa.y, SC2);
    u64 qA2 = mul2(qAb.x, SC2), qA3 = mul2(qAb.y, SC2);
    u64 qB0 = mul2(qBa.x, SC2), qB1 = mul2(qBa.y, SC2);
    u64 qB2 = mul2(qBb.x, SC2), qB3 = mul2(qBb.y, SC2);

    u64 aA0 = 0, aA1 = 0, aA2 = 0, aA3 = 0, dA = 0;
    u64 aB0 = 0, aB1 = 0, aB2 = 0, aB3 = 0, dB = 0;

    const int k0 = s * (TT / KSPLIT);
    // |exp2 arg| <= 4*0.72 < 3 : no max subtraction needed.
#pragma unroll 1
    for (int k = k0; k < k0 + TT / KSPLIT; k++) {
        ulonglong2 ka = Kpk[k][0];
        ulonglong2 kb = Kpk[k][1];
        // query A
        u64 sA = mul2(qA0, ka.x);
        sA = fma2(qA1, ka.y, sA);
        sA = fma2(qA2, kb.x, sA);
        sA = fma2(qA3, kb.y, sA);
        // query B
        u64 sB = mul2(qB0, ka.x);
        sB = fma2(qB1, ka.y, sB);
        sB = fma2(qB2, kb.x, sB);
        sB = fma2(qB3, kb.y, sB);
        float a0, a1, b0f, b1f;
        unpack2(sA, a0, a1);
        unpack2(sB, b0f, b1f);
        u64 eA = pack2(ex2(a0), ex2(a1));
        u64 eB = pack2(ex2(b0f), ex2(b1f));
        aA0 = fma2(eA, ka.x, aA0);
        aA1 = fma2(eA, ka.y, aA1);
        aA2 = fma2(eA, kb.x, aA2);
        aA3 = fma2(eA, kb.y, aA3);
        dA  = add2(dA, eA);
        aB0 = fma2(eB, ka.x, aB0);
        aB1 = fma2(eB, ka.y, aB1);
        aB2 = fma2(eB, kb.x, aB2);
        aB3 = fma2(eB, kb.y, aB3);
        dB  = add2(dB, eB);
    }

    // Combine the 4 key-splits (lanes differing in bits 0-1). After this,
    // every split lane holds the full sums.
#pragma unroll
    for (int d = 1; d < KSPLIT; d <<= 1) {
        aA0 = add2(aA0, __shfl_xor_sync(0xffffffffu, aA0, d));
        aA1 = add2(aA1, __shfl_xor_sync(0xffffffffu, aA1, d));
        aA2 = add2(aA2, __shfl_xor_sync(0xffffffffu, aA2, d));
        aA3 = add2(aA3, __shfl_xor_sync(0xffffffffu, aA3, d));
        dA  = add2(dA,  __shfl_xor_sync(0xffffffffu, dA,  d));
        aB0 = add2(aB0, __shfl_xor_sync(0xffffffffu, aB0, d));
        aB1 = add2(aB1, __shfl_xor_sync(0xffffffffu, aB1, d));
        aB2 = add2(aB2, __shfl_xor_sync(0xffffffffu, aB2, d));
        aB3 = add2(aB3, __shfl_xor_sync(0xffffffffu, aB3, d));
        dB  = add2(dB,  __shfl_xor_sync(0xffffffffu, dB,  d));
    }

    // Split lane 0 finalizes query A, split lane 1 finalizes query B.
    if (s == 0) {
        float d0, d1; unpack2(dA, d0, d1);
        float inv0 = __fdividef(1.0f, d0);
        float inv1 = __fdividef(1.0f, d1);
        float ctx[8], lo, hi;
        unpack2(aA0, lo, hi); ctx[0] = lo * inv0; ctx[4] = hi * inv1;
        unpack2(aA1, lo, hi); ctx[1] = lo * inv0; ctx[5] = hi * inv1;
        unpack2(aA2, lo, hi); ctx[2] = lo * inv0; ctx[6] = hi * inv1;
        unpack2(aA3, lo, hi); ctx[3] = lo * inv0; ctx[7] = hi * inv1;
        size_t row = (size_t)(b * TT + qi0);
        epilogue_row(ctx, x + row * 8, out + row * 8, C);
    } else if (s == 1) {
        float d0, d1; unpack2(dB, d0, d1);
        float inv0 = __fdividef(1.0f, d0);
        float inv1 = __fdividef(1.0f, d1);
        float ctx[8], lo, hi;
        unpack2(aB0, lo, hi); ctx[0] = lo * inv0; ctx[4] = hi * inv1;
        unpack2(aB1, lo, hi); ctx[1] = lo * inv0; ctx[5] = hi * inv1;
        unpack2(aB2, lo, hi); ctx[2] = lo * inv0; ctx[6] = hi * inv1;
        unpack2(aB3, lo, hi); ctx[3] = lo * inv0; ctx[7] = hi * inv1;
        size_t row = (size_t)(b * TT + qi1);
        epilogue_row(ctx, x + row * 8, out + row * 8, C);
    }
}

extern "C" void kernel_launch(void* const* d_in, const int* in_sizes, int n_in,
                              void* d_out, int out_size) {
    const float* x           = (const float*)d_in[0];
    const float* thetas_attn = (const float*)d_in[1];
    const float* thetas_ffn  = (const float*)d_in[2];
    const float* W_in        = (const float*)d_in[3];
    const float* b_in        = (const float*)d_in[4];
    const float* W_out       = (const float*)d_in[5];
    const float* b_out       = (const float*)d_in[6];
    const float* ln1w        = (const float*)d_in[7];
    const float* ln1b        = (const float*)d_in[8];
    const float* ln2w        = (const float*)d_in[9];
    const float* ln2b        = (const float*)d_in[10];
    float* out = (float*)d_out;

    fused_kernel<<<128 * 8, 128>>>(x, thetas_attn, thetas_ffn,
                                   W_in, b_in, W_out, b_out,
                                   ln1w, ln1b, ln2w, ln2b, out);
}

// round 10
// speedup vs baseline: 2.0711x; 2.0711x over previous
#include <cuda_runtime.h>
#include <cuda_bf16.h>

// Problem: B=128, T=512, E=8, H=2, dk=4. N = B*T = 65536 rows.
#define TT 512

typedef unsigned long long u64;

// ---- f32x2 packed helpers ----------
__device__ __forceinline__ u64 pack2(float lo, float hi) {
    u64 r; asm("mov.b64 %0, {%1, %2};" : "=l"(r) : "f"(lo), "f"(hi)); return r;
}
__device__ __forceinline__ void unpack2(u64 v, float& lo, float& hi) {
    asm("mov.b64 {%0, %1}, %2;" : "=f"(lo), "=f"(hi) : "l"(v));
}
__device__ __forceinline__ u64 mul2(u64 a, u64 b) {
    u64 r; asm("mul.rn.f32x2 %0, %1, %2;" : "=l"(r) : "l"(a), "l"(b)); return r;
}
__device__ __forceinline__ u64 fma2(u64 a, u64 b, u64 c) {
    u64 r; asm("fma.rn.f32x2 %0, %1, %2, %3;" : "=l"(r) : "l"(a), "l"(b), "l"(c)); return r;
}
__device__ __forceinline__ u64 add2(u64 a, u64 b) {
    u64 r; asm("add.rn.f32x2 %0, %1, %2;" : "=l"(r) : "l"(a), "l"(b)); return r;
}
__device__ __forceinline__ float ex2(float x) {
    float r; asm("ex2.approx.ftz.f32 %0, %1;" : "=f"(r) : "f"(x)); return r;
}

// qlayer closed form: given c[w]=cos(alpha_w):
// out[0]=c1*...*c7 ; out[w>=1]=c0*...*cw
__device__ __forceinline__ void qlayer_from_cos(const float c[8], float o[8]) {
    float t = c[1] * c[2];
    t *= c[3]; t *= c[4]; t *= c[5]; t *= c[6]; t *= c[7];
    o[0] = t;
    float p = c[0] * c[1];
    o[1] = p;
    p *= c[2]; o[2] = p;
    p *= c[3]; o[3] = p;
    p *= c[4]; o[4] = p;
    p *= c[5]; o[5] = p;
    p *= c[6]; o[6] = p;
    p *= c[7]; o[7] = p;
}

struct SmemConsts {
    float Win[64], Wout[64];
    float bin[8], bout[8], l1w[8], l1b[8], l2w[8], l2b[8], tha[8], thf[8];
};

// Full per-row epilogue: ctx -> output row. noinline so its register
// pressure does not inflate the mainloop allocation.
__device__ __noinline__ void epilogue_row(
    const float* __restrict__ ctx, const float* __restrict__ xr,
    float* __restrict__ orow, const SmemConsts& C
) {
    float xv[8];
    {
        float4 e = *reinterpret_cast<const float4*>(xr);
        float4 f = *reinterpret_cast<const float4*>(xr + 4);
        xv[0]=e.x; xv[1]=e.y; xv[2]=e.z; xv[3]=e.w;
        xv[4]=f.x; xv[5]=f.y; xv[6]=f.z; xv[7]=f.w;
    }
    float c[8];
#pragma unroll
    for (int w = 0; w < 8; w++) c[w] = __cosf(ctx[w] + C.tha[w]);
    float ao[8];
    qlayer_from_cos(c, ao);

    float s[8], x1[8];
    float m = 0.0f;
#pragma unroll
    for (int w = 0; w < 8; w++) { s[w] = ao[w] + xv[w]; m += s[w]; }
    m *= 0.125f;
    float v = 0.0f;
#pragma unroll
    for (int w = 0; w < 8; w++) { float d = s[w] - m; v += d * d; }
    v *= 0.125f;
    float istd = rsqrtf(v + 1e-5f);
#pragma unroll
    for (int w = 0; w < 8; w++) x1[w] = (s[w] - m) * istd * C.l1w[w] + C.l1b[w];

    float hq[8];
#pragma unroll
    for (int i = 0; i < 8; i++) {
        float acc = C.bin[i];
#pragma unroll
        for (int j = 0; j < 8; j++) acc += x1[j] * C.Win[i * 8 + j];
        hq[i] = acc;
    }

    // ffn qlayer, wires [0,1,2,2,4,5,6,7]
    float cf[8];
    cf[0] = __cosf(hq[0] + C.thf[0]);
    cf[1] = __cosf(hq[1] + C.thf[1]);
    cf[2] = __cosf(hq[2] + hq[3] + C.thf[2]);
    cf[3] = __cosf(C.thf[3]);
    cf[4] = __cosf(hq[4] + C.thf[4]);
    cf[5] = __cosf(hq[5] + C.thf[5]);
    cf[6] = __cosf(hq[6] + C.thf[6]);
    cf[7] = __cosf(hq[7] + C.thf[7]);
    float qf[8];
    qlayer_from_cos(cf, qf);

    float s2[8];
    float m2 = 0.0f;
#pragma unroll
    for (int i = 0; i < 8; i++) {
        float acc = C.bout[i];
#pragma unroll
        for (int j = 0; j < 8; j++) acc += qf[j] * C.Wout[i * 8 + j];
        s2[i] = acc + x1[i];
        m2 += s2[i];
    }
    m2 *= 0.125f;
    float v2 = 0.0f;
#pragma unroll
    for (int i = 0; i < 8; i++) { float d = s2[i] - m2; v2 += d * d; }
    v2 *= 0.125f;
    float istd2 = rsqrtf(v2 + 1e-5f);

    float res[8];
#pragma unroll
    for (int i = 0; i < 8; i++)
        res[i] = (s2[i] - m2) * istd2 * C.l2w[i] + C.l2b[i];

    *reinterpret_cast<float4*>(orow)     = make_float4(res[0], res[1], res[2], res[3]);
    *reinterpret_cast<float4*>(orow + 4) = make_float4(res[4], res[5], res[6], res[7]);
}

// ---------------------------------------------------------------------------
// Fully fused kernel. grid = 1024 (128 batches x 8 chunks of 64 queries),
// block = 128 threads = 4 warps.
//   Warps 0-1: key-split 0 (keys [0,256));  warps 2-3: key-split 1 ([256,512)).
//   Lane owns ONE query (G=1): qi = chunk*64 + (tid & 63). Both heads ride
//   the f32x2 lanes (lo = head0, hi = head1).
// KEY POINT: within a warp every lane reads the SAME Kpk[k] each iteration
// -> pure smem broadcast (conflict degree 1). Rounds 3/8/9 lost 2-4x LDS
// throughput to same-bank conflicts between intra-warp key splits.
// Split-1 partials (5 u64) pass through smem; split-0 threads combine and
// run the epilogue.
// ---------------------------------------------------------------------------
__global__ __launch_bounds__(128, 7) void fused_kernel(
    const float* __restrict__ x,
    const float* __restrict__ thetas_attn,
    const float* __restrict__ thetas_ffn,
    const float* __restrict__ W_in,
    const float* __restrict__ b_in,
    const float* __restrict__ W_out,
    const float* __restrict__ b_out,
    const float* __restrict__ ln1w, const float* __restrict__ ln1b,
    const float* __restrict__ ln2w, const float* __restrict__ ln2b,
    float* __restrict__ out
) {
    __shared__ ulonglong2 Kpk[TT][2];   // 16 KB lane-packed keys (h0_d, h1_d)
    __shared__ u64 part[5][64];         // 2.5 KB split-1 partials
    __shared__ SmemConsts C;

    const int tid   = threadIdx.x;
    const int b     = blockIdx.x >> 3;
    const int chunk = blockIdx.x & 7;

    if (tid < 64) { C.Win[tid] = W_in[tid]; C.Wout[tid] = W_out[tid]; }
    else if (tid < 72) {
        int i = tid - 64;
        C.bin[i] = b_in[i];  C.bout[i] = b_out[i];
        C.l1w[i] = ln1w[i];  C.l1b[i] = ln1b[i];
        C.l2w[i] = ln2w[i];  C.l2b[i] = ln2b[i];
        C.tha[i] = thetas_attn[i]; C.thf[i] = thetas_ffn[i];
    }

    float th[8];
#pragma unroll
    for (int w = 0; w < 8; w++) th[w] = thetas_attn[w];

    // Prologue: build all 512 keys (both heads) for this batch.
#pragma unroll
    for (int rr = 0; rr < TT / 128; rr++) {
        int i = tid + rr * 128;
        const float* xr = x + ((size_t)(b * TT + i)) * 8;
        float4 xa = *reinterpret_cast<const float4*>(xr);
        float4 xb = *reinterpret_cast<const float4*>(xr + 4);
        float c[8];
        c[0] = __cosf(xa.x + th[0]);
        c[1] = __cosf(xa.y + th[1]);
        c[2] = __cosf(xa.z + th[2]);
        c[3] = __cosf(xa.w + th[3]);
        c[4] = __cosf(xb.x + th[4]);
        c[5] = __cosf(xb.y + th[5]);
        c[6] = __cosf(xb.z + th[6]);
        c[7] = __cosf(xb.w + th[7]);
        float o[8];
        qlayer_from_cos(c, o);
        ulonglong2 p0, p1;
        p0.x = pack2(o[0], o[4]);
        p0.y = pack2(o[1], o[5]);
        p1.x = pack2(o[2], o[6]);
        p1.y = pack2(o[3], o[7]);
        Kpk[i][0] = p0;
        Kpk[i][1] = p1;
    }
    __syncthreads();

    const int split = tid >> 6;            // warps 0-1 -> 0, warps 2-3 -> 1
    const int qloc  = tid & 63;            // query within chunk
    const int qi    = chunk * 64 + qloc;

    // Query pre-scaled by 0.5*log2(e) (softmax scale 1/sqrt(dk)=0.5 folded).
    const float SC = 0.72134752044f;
    const u64 SC2 = pack2(SC, SC);
    ulonglong2 qa = Kpk[qi][0], qb = Kpk[qi][1];
    u64 qp0 = mul2(qa.x, SC2), qp1 = mul2(qa.y, SC2);
    u64 qp2 = mul2(qb.x, SC2), qp3 = mul2(qb.y, SC2);

    u64 acc0 = 0, acc1 = 0, acc2 = 0, acc3 = 0, dn = 0;

    const int k0 = split * (TT / 2);
    // |exp2 arg| <= 4*0.72 < 3 : no max subtraction needed.
#pragma unroll 1
    for (int k = k0; k < k0 + TT / 2; k++) {
        ulonglong2 ka = Kpk[k][0];   // warp-uniform address -> broadcast
        ulonglong2 kb = Kpk[k][1];
        u64 s = mul2(qp0, ka.x);
        s = fma2(qp1, ka.y, s);
        s = fma2(qp2, kb.x, s);
        s = fma2(qp3, kb.y, s);
        float s0, s1; unpack2(s, s0, s1);
        u64 e = pack2(ex2(s0), ex2(s1));
        acc0 = fma2(e, ka.x, acc0);
        acc1 = fma2(e, ka.y, acc1);
        acc2 = fma2(e, kb.x, acc2);
        acc3 = fma2(e, kb.y, acc3);
        dn   = add2(dn, e);
    }

    // Split 1 publishes partials; split 0 combines.
    if (split == 1) {
        part[0][qloc] = acc0;
        part[1][qloc] = acc1;
        part[2][qloc] = acc2;
        part[3][qloc] = acc3;
        part[4][qloc] = dn;
    }
    __syncthreads();

    if (split == 0) {
        acc0 = add2(acc0, part[0][qloc]);
        acc1 = add2(acc1, part[1][qloc]);
        acc2 = add2(acc2, part[2][qloc]);
        acc3 = add2(acc3, part[3][qloc]);
        dn   = add2(dn,   part[4][qloc]);

        float d0, d1; unpack2(dn, d0, d1);
        float inv0 = __fdividef(1.0f, d0);
        float inv1 = __fdividef(1.0f, d1);
        float ctx[8], lo, hi;
        unpack2(acc0, lo, hi); ctx[0] = lo * inv0; ctx[4] = hi * inv1;
        unpack2(acc1, lo, hi); ctx[1] = lo * inv0; ctx[5] = hi * inv1;
        unpack2(acc2, lo, hi); ctx[2] = lo * inv0; ctx[6] = hi * inv1;
        unpack2(acc3, lo, hi); ctx[3] = lo * inv0; ctx[7] = hi * inv1;

        size_t row = (size_t)(b * TT + qi);
        epilogue_row(ctx, x + row * 8, out + row * 8, C);
    }
}

extern "C" void kernel_launch(void* const* d_in, const int* in_sizes, int n_in,
                              void* d_out, int out_size) {
    const float* x           = (const float*)d_in[0];
    const float* thetas_attn = (const float*)d_in[1];
    const float* thetas_ffn  = (const float*)d_in[2];
    const float* W_in        = (const float*)d_in[3];
    const float* b_in        = (const float*)d_in[4];
    const float* W_out       = (const float*)d_in[5];
    const float* b_out       = (const float*)d_in[6];
    const float* ln1w        = (const float*)d_in[7];
    const float* ln1b        = (const float*)d_in[8];
    const float* ln2w        = (const float*)d_in[9];
    const float* ln2b        = (const float*)d_in[10];
    float* out = (float*)d_out;

    fused_kernel<<<128 * 8, 128>>>(x, thetas_attn, thetas_ffn,
                                   W_in, b_in, W_out, b_out,
                                   ln1w, ln1b, ln2w, ln2b, out);
}

// round 11
// speedup vs baseline: 2.1755x; 1.0504x over previous
#include <cuda_runtime.h>
#include <cuda_bf16.h>

// Problem: B=128, T=512, E=8, H=2, dk=4. N = B*T = 65536 rows.
#define TT 512

typedef unsigned long long u64;

// ---- f32x2 packed helpers ----------
__device__ __forceinline__ u64 pack2(float lo, float hi) {
    u64 r; asm("mov.b64 %0, {%1, %2};" : "=l"(r) : "f"(lo), "f"(hi)); return r;
}
__device__ __forceinline__ void unpack2(u64 v, float& lo, float& hi) {
    asm("mov.b64 {%0, %1}, %2;" : "=f"(lo), "=f"(hi) : "l"(v));
}
__device__ __forceinline__ u64 mul2(u64 a, u64 b) {
    u64 r; asm("mul.rn.f32x2 %0, %1, %2;" : "=l"(r) : "l"(a), "l"(b)); return r;
}
__device__ __forceinline__ u64 fma2(u64 a, u64 b, u64 c) {
    u64 r; asm("fma.rn.f32x2 %0, %1, %2, %3;" : "=l"(r) : "l"(a), "l"(b), "l"(c)); return r;
}
__device__ __forceinline__ u64 add2(u64 a, u64 b) {
    u64 r; asm("add.rn.f32x2 %0, %1, %2;" : "=l"(r) : "l"(a), "l"(b)); return r;
}
__device__ __forceinline__ float ex2(float x) {
    float r; asm("ex2.approx.ftz.f32 %0, %1;" : "=f"(r) : "f"(x)); return r;
}

// qlayer closed form: given c[w]=cos(alpha_w):
// out[0]=c1*...*c7 ; out[w>=1]=c0*...*cw
__device__ __forceinline__ void qlayer_from_cos(const float c[8], float o[8]) {
    float t = c[1] * c[2];
    t *= c[3]; t *= c[4]; t *= c[5]; t *= c[6]; t *= c[7];
    o[0] = t;
    float p = c[0] * c[1];
    o[1] = p;
    p *= c[2]; o[2] = p;
    p *= c[3]; o[3] = p;
    p *= c[4]; o[4] = p;
    p *= c[5]; o[5] = p;
    p *= c[6]; o[6] = p;
    p *= c[7]; o[7] = p;
}

struct SmemConsts {
    float Win[64], Wout[64];
    float bin[8], bout[8], l1w[8], l1b[8], l2w[8], l2b[8], tha[8], thf[8];
};

// Full per-row epilogue: ctx -> output row. noinline so its register
// pressure does not inflate the mainloop allocation.
__device__ __noinline__ void epilogue_row(
    const float* __restrict__ ctx, const float* __restrict__ xr,
    float* __restrict__ orow, const SmemConsts& C
) {
    float xv[8];
    {
        float4 e = *reinterpret_cast<const float4*>(xr);
        float4 f = *reinterpret_cast<const float4*>(xr + 4);
        xv[0]=e.x; xv[1]=e.y; xv[2]=e.z; xv[3]=e.w;
        xv[4]=f.x; xv[5]=f.y; xv[6]=f.z; xv[7]=f.w;
    }
    float c[8];
#pragma unroll
    for (int w = 0; w < 8; w++) c[w] = __cosf(ctx[w] + C.tha[w]);
    float ao[8];
    qlayer_from_cos(c, ao);

    float s[8], x1[8];
    float m = 0.0f;
#pragma unroll
    for (int w = 0; w < 8; w++) { s[w] = ao[w] + xv[w]; m += s[w]; }
    m *= 0.125f;
    float v = 0.0f;
#pragma unroll
    for (int w = 0; w < 8; w++) { float d = s[w] - m; v += d * d; }
    v *= 0.125f;
    float istd = rsqrtf(v + 1e-5f);
#pragma unroll
    for (int w = 0; w < 8; w++) x1[w] = (s[w] - m) * istd * C.l1w[w] + C.l1b[w];

    float hq[8];
#pragma unroll
    for (int i = 0; i < 8; i++) {
        float acc = C.bin[i];
#pragma unroll
        for (int j = 0; j < 8; j++) acc += x1[j] * C.Win[i * 8 + j];
        hq[i] = acc;
    }

    // ffn qlayer, wires [0,1,2,2,4,5,6,7]
    float cf[8];
    cf[0] = __cosf(hq[0] + C.thf[0]);
    cf[1] = __cosf(hq[1] + C.thf[1]);
    cf[2] = __cosf(hq[2] + hq[3] + C.thf[2]);
    cf[3] = __cosf(C.thf[3]);
    cf[4] = __cosf(hq[4] + C.thf[4]);
    cf[5] = __cosf(hq[5] + C.thf[5]);
    cf[6] = __cosf(hq[6] + C.thf[6]);
    cf[7] = __cosf(hq[7] + C.thf[7]);
    float qf[8];
    qlayer_from_cos(cf, qf);

    float s2[8];
    float m2 = 0.0f;
#pragma unroll
    for (int i = 0; i < 8; i++) {
        float acc = C.bout[i];
#pragma unroll
        for (int j = 0; j < 8; j++) acc += qf[j] * C.Wout[i * 8 + j];
        s2[i] = acc + x1[i];
        m2 += s2[i];
    }
    m2 *= 0.125f;
    float v2 = 0.0f;
#pragma unroll
    for (int i = 0; i < 8; i++) { float d = s2[i] - m2; v2 += d * d; }
    v2 *= 0.125f;
    float istd2 = rsqrtf(v2 + 1e-5f);

    float res[8];
#pragma unroll
    for (int i = 0; i < 8; i++)
        res[i] = (s2[i] - m2) * istd2 * C.l2w[i] + C.l2b[i];

    *reinterpret_cast<float4*>(orow)     = make_float4(res[0], res[1], res[2], res[3]);
    *reinterpret_cast<float4*>(orow + 4) = make_float4(res[4], res[5], res[6], res[7]);
}

// ---------------------------------------------------------------------------
// Fully fused kernel. grid = 1024 (128 batches x 8 chunks of 64 queries),
// block = 128 threads = 4 warps.
//   Warps 0-1: key-split 0 (keys [0,256));  warps 2-3: key-split 1 ([256,512)).
//   Lane owns ONE query: qi = chunk*64 + (tid & 63). Both heads ride the
//   f32x2 lanes (lo = head0, hi = head1). Within a warp every lane reads the
//   SAME Kpk[k] -> pure smem broadcast (conflict degree 1).
// Round-11 change: mainloop manually software-pipelined over TWO keys with
// fully independent chains (2 scores, 2 exps, 2 denominators) so each warp
// exposes ~2x issueable instructions per dependency window. Register cap
// raised to 85 via launch_bounds(128,6) to fit the extra live state
// (round-10 loop sat at 72/73 with zero pipelining headroom).
// ---------------------------------------------------------------------------
__global__ __launch_bounds__(128, 6) void fused_kernel(
    const float* __restrict__ x,
    const float* __restrict__ thetas_attn,
    const float* __restrict__ thetas_ffn,
    const float* __restrict__ W_in,
    const float* __restrict__ b_in,
    const float* __restrict__ W_out,
    const float* __restrict__ b_out,
    const float* __restrict__ ln1w, const float* __restrict__ ln1b,
    const float* __restrict__ ln2w, const float* __restrict__ ln2b,
    float* __restrict__ out
) {
    __shared__ ulonglong2 Kpk[TT][2];   // 16 KB lane-packed keys (h0_d, h1_d)
    __shared__ u64 part[5][64];         // 2.5 KB split-1 partials
    __shared__ SmemConsts C;

    const int tid   = threadIdx.x;
    const int b     = blockIdx.x >> 3;
    const int chunk = blockIdx.x & 7;

    if (tid < 64) { C.Win[tid] = W_in[tid]; C.Wout[tid] = W_out[tid]; }
    else if (tid < 72) {
        int i = tid - 64;
        C.bin[i] = b_in[i];  C.bout[i] = b_out[i];
        C.l1w[i] = ln1w[i];  C.l1b[i] = ln1b[i];
        C.l2w[i] = ln2w[i];  C.l2b[i] = ln2b[i];
        C.tha[i] = thetas_attn[i]; C.thf[i] = thetas_ffn[i];
    }

    float th[8];
#pragma unroll
    for (int w = 0; w < 8; w++) th[w] = thetas_attn[w];

    // Prologue: build all 512 keys (both heads) for this batch.
#pragma unroll
    for (int rr = 0; rr < TT / 128; rr++) {
        int i = tid + rr * 128;
        const float* xr = x + ((size_t)(b * TT + i)) * 8;
        float4 xa = *reinterpret_cast<const float4*>(xr);
        float4 xb = *reinterpret_cast<const float4*>(xr + 4);
        float c[8];
        c[0] = __cosf(xa.x + th[0]);
        c[1] = __cosf(xa.y + th[1]);
        c[2] = __cosf(xa.z + th[2]);
        c[3] = __cosf(xa.w + th[3]);
        c[4] = __cosf(xb.x + th[4]);
        c[5] = __cosf(xb.y + th[5]);
        c[6] = __cosf(xb.z + th[6]);
        c[7] = __cosf(xb.w + th[7]);
        float o[8];
        qlayer_from_cos(c, o);
        ulonglong2 p0, p1;
        p0.x = pack2(o[0], o[4]);
        p0.y = pack2(o[1], o[5]);
        p1.x = pack2(o[2], o[6]);
        p1.y = pack2(o[3], o[7]);
        Kpk[i][0] = p0;
        Kpk[i][1] = p1;
    }
    __syncthreads();

    const int split = tid >> 6;            // warps 0-1 -> 0, warps 2-3 -> 1
    const int qloc  = tid & 63;            // query within chunk
    const int qi    = chunk * 64 + qloc;

    // Query pre-scaled by 0.5*log2(e) (softmax scale 1/sqrt(dk)=0.5 folded).
    const float SC = 0.72134752044f;
    const u64 SC2 = pack2(SC, SC);
    ulonglong2 qa = Kpk[qi][0], qb = Kpk[qi][1];
    u64 qp0 = mul2(qa.x, SC2), qp1 = mul2(qa.y, SC2);
    u64 qp2 = mul2(qb.x, SC2), qp3 = mul2(qb.y, SC2);

    u64 acc0 = 0, acc1 = 0, acc2 = 0, acc3 = 0;
    u64 dn0 = 0, dn1 = 0;

    const int k0 = split * (TT / 2);
    // |exp2 arg| <= 4*0.72 < 3 : no max subtraction needed.
    // Two independent key chains per iteration (software pipelining).
#pragma unroll 1
    for (int k = k0; k < k0 + TT / 2; k += 2) {
        ulonglong2 kaX = Kpk[k][0];      // warp-uniform -> broadcast
        ulonglong2 kbX = Kpk[k][1];
        ulonglong2 kaY = Kpk[k + 1][0];
        ulonglong2 kbY = Kpk[k + 1][1];

        u64 sX = mul2(qp0, kaX.x);
        u64 sY = mul2(qp0, kaY.x);
        sX = fma2(qp1, kaX.y, sX);
        sY = fma2(qp1, kaY.y, sY);
        sX = fma2(qp2, kbX.x, sX);
        sY = fma2(qp2, kbY.x, sY);
        sX = fma2(qp3, kbX.y, sX);
        sY = fma2(qp3, kbY.y, sY);

        float x0, x1f, y0, y1;
        unpack2(sX, x0, x1f);
        unpack2(sY, y0, y1);
        u64 eX = pack2(ex2(x0), ex2(x1f));
        u64 eY = pack2(ex2(y0), ex2(y1));

        acc0 = fma2(eX, kaX.x, acc0);
        acc1 = fma2(eX, kaX.y, acc1);
        acc2 = fma2(eX, kbX.x, acc2);
        acc3 = fma2(eX, kbX.y, acc3);
        dn0  = add2(dn0, eX);
        acc0 = fma2(eY, kaY.x, acc0);
        acc1 = fma2(eY, kaY.y, acc1);
        acc2 = fma2(eY, kbY.x, acc2);
        acc3 = fma2(eY, kbY.y, acc3);
        dn1  = add2(dn1, eY);
    }
    u64 dn = add2(dn0, dn1);

    // Split 1 publishes partials; split 0 combines.
    if (split == 1) {
        part[0][qloc] = acc0;
        part[1][qloc] = acc1;
        part[2][qloc] = acc2;
        part[3][qloc] = acc3;
        part[4][qloc] = dn;
    }
    __syncthreads();

    if (split == 0) {
        acc0 = add2(acc0, part[0][qloc]);
        acc1 = add2(acc1, part[1][qloc]);
        acc2 = add2(acc2, part[2][qloc]);
        acc3 = add2(acc3, part[3][qloc]);
        dn   = add2(dn,   part[4][qloc]);

        float d0, d1; unpack2(dn, d0, d1);
        float inv0 = __fdividef(1.0f, d0);
        float inv1 = __fdividef(1.0f, d1);
        float ctx[8], lo, hi;
        unpack2(acc0, lo, hi); ctx[0] = lo * inv0; ctx[4] = hi * inv1;
        unpack2(acc1, lo, hi); ctx[1] = lo * inv0; ctx[5] = hi * inv1;
        unpack2(acc2, lo, hi); ctx[2] = lo * inv0; ctx[6] = hi * inv1;
        unpack2(acc3, lo, hi); ctx[3] = lo * inv0; ctx[7] = hi * inv1;

        size_t row = (size_t)(b * TT + qi);
        epilogue_row(ctx, x + row * 8, out + row * 8, C);
    }
}

extern "C" void kernel_launch(void* const* d_in, const int* in_sizes, int n_in,
                              void* d_out, int out_size) {
    const float* x           = (const float*)d_in[0];
    const float* thetas_attn = (const float*)d_in[1];
    const float* thetas_ffn  = (const float*)d_in[2];
    const float* W_in        = (const float*)d_in[3];
    const float* b_in        = (const float*)d_in[4];
    const float* W_out       = (const float*)d_in[5];
    const float* b_out       = (const float*)d_in[6];
    const float* ln1w        = (const float*)d_in[7];
    const float* ln1b        = (const float*)d_in[8];
    const float* ln2w        = (const float*)d_in[9];
    const float* ln2b        = (const float*)d_in[10];
    float* out = (float*)d_out;

    fused_kernel<<<128 * 8, 128>>>(x, thetas_attn, thetas_ffn,
                                   W_in, b_in, W_out, b_out,
                                   ln1w, ln1b, ln2w, ln2b, out);
}